// round 5
// baseline (speedup 1.0000x reference)
#include <cuda_runtime.h>
#include <cuda_bf16.h>
#include <cstdint>

#define N_NODES 100000
#define N_EDGES 3200000
#define IN_DIM  256
#define HID_DIM 128
#define OUT_DIM 64

#define SCAN_BLK 1024
#define N_SCAN_BLOCKS ((N_NODES + SCAN_BLK - 1) / SCAN_BLK)   // 98

// ---------------- device scratch (static: no runtime allocation) -------------
__device__ int   g_is64;                   // 1 if edge_index is int64, else int32
__device__ int   g_src[N_EDGES];           // normalized src indices
__device__ int   g_dst[N_EDGES];           // normalized dst indices
__device__ int   g_ecnt[N_NODES];          // in-edge count per node (excl. self loop)
__device__ float g_dis[N_NODES];           // deg^{-1/2} with self loop
__device__ int   g_rowptr[N_NODES + 1];    // CSR row pointers (by dst)
__device__ int   g_cur[N_NODES];           // scatter cursors
__device__ int   g_col[N_EDGES];           // CSR column indices (src node)
__device__ int   g_bsum[N_SCAN_BLOCKS];    // scan partials
__device__ int   g_bofs[N_SCAN_BLOCKS];    // scanned partials
__device__ float g_h[(size_t)N_NODES * HID_DIM];  // transform output
__device__ float g_a[(size_t)N_NODES * HID_DIM];  // aggregate output

// ---------------- edge dtype detection + normalization ------------------------
// If int64 (values < 2^17), every odd 32-bit word is 0. If int32, odd words are
// random node ids; P(all 64 probes zero) ~ (1e-5)^64 ~ 0.
__global__ void k_detect(const int* __restrict__ ei32) {
    __shared__ int nz;
    if (threadIdx.x == 0) nz = 0;
    __syncthreads();
    // probe odd words among the first 128 words (always in-bounds: >= 6.4M words)
    int idx = 2 * threadIdx.x + 1;          // threadIdx.x in [0,64)
    if (threadIdx.x < 64 && ei32[idx] != 0) atomicAdd(&nz, 1);
    __syncthreads();
    if (threadIdx.x == 0) g_is64 = (nz == 0) ? 1 : 0;
}

__global__ void k_convert(const void* __restrict__ ei) {
    int e = blockIdx.x * blockDim.x + threadIdx.x;
    if (e >= N_EDGES) return;
    int s, d;
    if (g_is64) {
        const long long* p = (const long long*)ei;
        s = (int)p[e];
        d = (int)p[N_EDGES + e];
    } else {
        const int* p = (const int*)ei;
        s = p[e];
        d = p[N_EDGES + e];
    }
    g_src[e] = s;
    g_dst[e] = d;
}

// ---------------- CSR build ---------------------------------------------------
__global__ void k_zero_ecnt() {
    int i = blockIdx.x * blockDim.x + threadIdx.x;
    if (i < N_NODES) g_ecnt[i] = 0;
}

__global__ void k_hist() {
    int e = blockIdx.x * blockDim.x + threadIdx.x;
    if (e < N_EDGES) {
        int dst = g_dst[e];
        if ((unsigned)dst < N_NODES) atomicAdd(&g_ecnt[dst], 1);
    }
}

__global__ void k_dis() {
    int i = blockIdx.x * blockDim.x + threadIdx.x;
    if (i < N_NODES) g_dis[i] = rsqrtf((float)(g_ecnt[i] + 1));
}

// block-level exclusive scan (Hillis-Steele, 1024 elems/block)
__global__ void k_scanA() {
    __shared__ int s[SCAN_BLK];
    int gid = blockIdx.x * SCAN_BLK + threadIdx.x;
    int v = (gid < N_NODES) ? g_ecnt[gid] : 0;
    s[threadIdx.x] = v;
    __syncthreads();
    #pragma unroll
    for (int d = 1; d < SCAN_BLK; d <<= 1) {
        int t = (threadIdx.x >= d) ? s[threadIdx.x - d] : 0;
        __syncthreads();
        s[threadIdx.x] += t;
        __syncthreads();
    }
    if (gid < N_NODES) g_rowptr[gid] = s[threadIdx.x] - v;  // exclusive
    if (threadIdx.x == SCAN_BLK - 1) g_bsum[blockIdx.x] = s[SCAN_BLK - 1];
}

__global__ void k_scanB() {
    if (threadIdx.x == 0) {
        int run = 0;
        for (int b = 0; b < N_SCAN_BLOCKS; b++) {
            g_bofs[b] = run;
            run += g_bsum[b];
        }
    }
}

__global__ void k_scanC() {
    int i = blockIdx.x * blockDim.x + threadIdx.x;
    if (i < N_NODES) {
        int r = g_rowptr[i] + g_bofs[i / SCAN_BLK];
        g_rowptr[i] = r;
        g_cur[i] = r;
    }
    if (i == 0) g_rowptr[N_NODES] = N_EDGES;
}

__global__ void k_scatter() {
    int e = blockIdx.x * blockDim.x + threadIdx.x;
    if (e < N_EDGES) {
        int src = g_src[e];
        int dst = g_dst[e];
        if ((unsigned)dst < N_NODES && (unsigned)src < N_NODES) {
            int pos = atomicAdd(&g_cur[dst], 1);
            g_col[pos] = src;
        }
    }
}

// ---------------- SGEMM: C[M,BN] = A[M,K] @ B[K,BN]  (N == BN exactly) -------
template <int BN, int TN>
__global__ __launch_bounds__(256) void gemm_tiled(
    const float* __restrict__ A, const float* __restrict__ B,
    float* __restrict__ C, int M, int K)
{
    constexpr int BM = 128, BK = 16, TM = 8;
    constexpr int TX = BN / TN;   // 16
    __shared__ float As[BK][BM];
    __shared__ float Bs[BK][BN];

    int tid = threadIdx.x;
    int tx = tid % TX;
    int ty = tid / TX;            // 0..15
    int row0 = blockIdx.x * BM;

    float acc[TM][TN];
    #pragma unroll
    for (int i = 0; i < TM; i++)
        #pragma unroll
        for (int j = 0; j < TN; j++) acc[i][j] = 0.f;

    for (int kt = 0; kt < K; kt += BK) {
        // A tile: 128 rows x 16 k, float4 along K, stored transposed
        #pragma unroll
        for (int it = 0; it < 2; it++) {
            int r  = tid / 4 + it * 64;
            int kk = (tid % 4) * 4;
            int grow = row0 + r;
            float4 v = make_float4(0.f, 0.f, 0.f, 0.f);
            if (grow < M)
                v = *(const float4*)&A[(size_t)grow * K + kt + kk];
            As[kk + 0][r] = v.x;
            As[kk + 1][r] = v.y;
            As[kk + 2][r] = v.z;
            As[kk + 3][r] = v.w;
        }
        // B tile: BK x BN
        #pragma unroll
        for (int i = tid; i < BK * BN / 4; i += 256) {
            int kk = (i * 4) / BN;
            int nn = (i * 4) % BN;
            *(float4*)&Bs[kk][nn] = *(const float4*)&B[(size_t)(kt + kk) * BN + nn];
        }
        __syncthreads();

        #pragma unroll
        for (int k = 0; k < BK; k++) {
            float a[TM], b[TN];
            #pragma unroll
            for (int i = 0; i < TM; i++) a[i] = As[k][ty * TM + i];
            #pragma unroll
            for (int j = 0; j < TN; j++) b[j] = Bs[k][tx * TN + j];
            #pragma unroll
            for (int i = 0; i < TM; i++)
                #pragma unroll
                for (int j = 0; j < TN; j++)
                    acc[i][j] = fmaf(a[i], b[j], acc[i][j]);
        }
        __syncthreads();
    }

    #pragma unroll
    for (int i = 0; i < TM; i++) {
        int grow = row0 + ty * TM + i;
        if (grow < M) {
            #pragma unroll
            for (int j = 0; j < TN; j += 4) {
                float4 v = make_float4(acc[i][j], acc[i][j + 1],
                                       acc[i][j + 2], acc[i][j + 3]);
                *(float4*)&C[(size_t)grow * BN + tx * TN + j] = v;
            }
        }
    }
}

// ---------------- aggregation: out[i] = dis[i]*(dis[i]*h_i + sum dis[j]*h_j)+b
// one warp per dst node, lane owns a float4 chunk of the F-dim row
template <int F, bool RELU>
__global__ __launch_bounds__(128) void agg_kernel(
    const float* __restrict__ h, float* __restrict__ out,
    const float* __restrict__ bias)
{
    int warp = (blockIdx.x * blockDim.x + threadIdx.x) >> 5;
    int lane = threadIdx.x & 31;
    if (warp >= N_NODES) return;

    constexpr int NCHUNK = F / 4;
    bool active = (NCHUNK == 32) || (lane < NCHUNK);

    float di = g_dis[warp];
    float4 acc = make_float4(0.f, 0.f, 0.f, 0.f);
    if (active) {
        float4 t = *(const float4*)&h[(size_t)warp * F + lane * 4];
        acc.x = di * t.x; acc.y = di * t.y; acc.z = di * t.z; acc.w = di * t.w;
    }

    int p   = g_rowptr[warp];
    int end = g_rowptr[warp + 1];

    // 4-edge unroll for MLP
    for (; p + 4 <= end; p += 4) {
        int j0 = __ldg(&g_col[p + 0]);
        int j1 = __ldg(&g_col[p + 1]);
        int j2 = __ldg(&g_col[p + 2]);
        int j3 = __ldg(&g_col[p + 3]);
        float w0 = __ldg(&g_dis[j0]);
        float w1 = __ldg(&g_dis[j1]);
        float w2 = __ldg(&g_dis[j2]);
        float w3 = __ldg(&g_dis[j3]);
        if (active) {
            float4 t0 = *(const float4*)&h[(size_t)j0 * F + lane * 4];
            float4 t1 = *(const float4*)&h[(size_t)j1 * F + lane * 4];
            float4 t2 = *(const float4*)&h[(size_t)j2 * F + lane * 4];
            float4 t3 = *(const float4*)&h[(size_t)j3 * F + lane * 4];
            acc.x += w0 * t0.x + w1 * t1.x + w2 * t2.x + w3 * t3.x;
            acc.y += w0 * t0.y + w1 * t1.y + w2 * t2.y + w3 * t3.y;
            acc.z += w0 * t0.z + w1 * t1.z + w2 * t2.z + w3 * t3.z;
            acc.w += w0 * t0.w + w1 * t1.w + w2 * t2.w + w3 * t3.w;
        }
    }
    for (; p < end; p++) {
        int j = __ldg(&g_col[p]);
        float w = __ldg(&g_dis[j]);
        if (active) {
            float4 t = *(const float4*)&h[(size_t)j * F + lane * 4];
            acc.x += w * t.x; acc.y += w * t.y;
            acc.z += w * t.z; acc.w += w * t.w;
        }
    }

    if (active) {
        float4 b4 = *(const float4*)&bias[lane * 4];
        float4 o;
        o.x = di * acc.x + b4.x;
        o.y = di * acc.y + b4.y;
        o.z = di * acc.z + b4.z;
        o.w = di * acc.w + b4.w;
        if (RELU) {
            o.x = fmaxf(o.x, 0.f); o.y = fmaxf(o.y, 0.f);
            o.z = fmaxf(o.z, 0.f); o.w = fmaxf(o.w, 0.f);
        }
        *(float4*)&out[(size_t)warp * F + lane * 4] = o;
    }
}

// ---------------- launch ------------------------------------------------------
extern "C" void kernel_launch(void* const* d_in, const int* in_sizes, int n_in,
                              void* d_out, int out_size)
{
    const float* x  = (const float*)d_in[0];
    const void*  ei = d_in[1];                 // int32 or int64, detected on device
    const float* W1 = (const float*)d_in[2];
    const float* b1 = (const float*)d_in[3];
    const float* W2 = (const float*)d_in[4];
    const float* b2 = (const float*)d_in[5];
    const float* W3 = (const float*)d_in[6];
    const float* b3 = (const float*)d_in[7];
    float* out = (float*)d_out;

    // resolve device-symbol addresses (host-side, capture-safe: no alloc/sync)
    float *hbuf = nullptr, *abuf = nullptr;
    cudaGetSymbolAddress((void**)&hbuf, g_h);
    cudaGetSymbolAddress((void**)&abuf, g_a);

    const int TPB = 256;
    int nb_nodes = (N_NODES + TPB - 1) / TPB;
    int nb_edges = (N_EDGES + TPB - 1) / TPB;

    // --- edge dtype detect + normalize ---
    k_detect<<<1, 64>>>((const int*)ei);
    k_convert<<<nb_edges, TPB>>>(ei);

    // --- CSR build ---
    k_zero_ecnt<<<nb_nodes, TPB>>>();
    k_hist<<<nb_edges, TPB>>>();
    k_dis<<<nb_nodes, TPB>>>();
    k_scanA<<<N_SCAN_BLOCKS, SCAN_BLK>>>();
    k_scanB<<<1, 32>>>();
    k_scanC<<<nb_nodes, TPB>>>();
    k_scatter<<<nb_edges, TPB>>>();

    int gemm_blocks = (N_NODES + 127) / 128;
    int agg_blocks  = (N_NODES + 3) / 4;   // 4 warps per 128-thread block

    // --- layer 1: x[100000,256] @ W1[256,128] -> agg + relu ---
    gemm_tiled<128, 8><<<gemm_blocks, 256>>>(x, W1, hbuf, N_NODES, IN_DIM);
    agg_kernel<128, true><<<agg_blocks, 128>>>(hbuf, abuf, b1);

    // --- layer 2: a[100000,128] @ W2[128,128] -> agg + relu ---
    gemm_tiled<128, 8><<<gemm_blocks, 256>>>(abuf, W2, hbuf, N_NODES, HID_DIM);
    agg_kernel<128, true><<<agg_blocks, 128>>>(hbuf, abuf, b2);

    // --- layer 3: a[100000,128] @ W3[128,64] -> agg (no relu), write d_out ---
    gemm_tiled<64, 4><<<gemm_blocks, 256>>>(abuf, W3, hbuf, N_NODES, HID_DIM);
    agg_kernel<64, false><<<agg_blocks, 128>>>(hbuf, out, b3);
}

// round 6
// speedup vs baseline: 1.3573x; 1.3573x over previous
#include <cuda_runtime.h>
#include <cuda_fp16.h>
#include <mma.h>
#include <cstdint>

using namespace nvcuda;

#define N_NODES 100000
#define N_EDGES 3200000
#define IN_DIM  256
#define HID_DIM 128
#define OUT_DIM 64
#define M_PAD   100096          // 782 * 128, so WMMA stores need no tail guard

#define SCAN_BLK 1024
#define N_SCAN_BLOCKS ((N_NODES + SCAN_BLK - 1) / SCAN_BLK)   // 98

// ---------------- device scratch (static: no runtime allocation) -------------
__device__ int    g_is64;
__device__ int    g_src[N_EDGES];
__device__ int    g_dst[N_EDGES];
__device__ int    g_ecnt[N_NODES];
__device__ float  g_dis[N_NODES];
__device__ int    g_rowptr[N_NODES + 1];
__device__ int    g_cur[N_NODES];
__device__ int    g_col[N_EDGES];
__device__ int    g_bsum[N_SCAN_BLOCKS];
__device__ int    g_bofs[N_SCAN_BLOCKS];
__device__ __half g_h[(size_t)M_PAD * HID_DIM];   // GEMM output (gather operand), fp16
__device__ float  g_a[(size_t)M_PAD * HID_DIM];   // aggregation output (GEMM input), fp32

// ---------------- edge dtype detection ----------------------------------------
// int64 values < 2^17 -> every odd 32-bit word is 0; int32 -> odd words random.
__global__ void k_detect(const int* __restrict__ ei32) {
    __shared__ int nz;
    if (threadIdx.x == 0) nz = 0;
    __syncthreads();
    int idx = 2 * threadIdx.x + 1;
    if (threadIdx.x < 64 && ei32[idx] != 0) atomicAdd(&nz, 1);
    __syncthreads();
    if (threadIdx.x == 0) g_is64 = (nz == 0) ? 1 : 0;
}

__global__ void k_zero_ecnt() {
    int i = blockIdx.x * blockDim.x + threadIdx.x;
    if (i < N_NODES) g_ecnt[i] = 0;
}

// fused: normalize edge dtype + in-degree histogram (one pass over edge_index)
__global__ void k_prep(const void* __restrict__ ei) {
    int e = blockIdx.x * blockDim.x + threadIdx.x;
    if (e >= N_EDGES) return;
    int s, d;
    if (g_is64) {
        const long long* p = (const long long*)ei;
        s = (int)p[e];
        d = (int)p[N_EDGES + e];
    } else {
        const int* p = (const int*)ei;
        s = p[e];
        d = p[N_EDGES + e];
    }
    g_src[e] = s;
    g_dst[e] = d;
    if ((unsigned)d < N_NODES) atomicAdd(&g_ecnt[d], 1);
}

__global__ void k_dis() {
    int i = blockIdx.x * blockDim.x + threadIdx.x;
    if (i < N_NODES) g_dis[i] = rsqrtf((float)(g_ecnt[i] + 1));
}

__global__ void k_scanA() {
    __shared__ int s[SCAN_BLK];
    int gid = blockIdx.x * SCAN_BLK + threadIdx.x;
    int v = (gid < N_NODES) ? g_ecnt[gid] : 0;
    s[threadIdx.x] = v;
    __syncthreads();
    #pragma unroll
    for (int d = 1; d < SCAN_BLK; d <<= 1) {
        int t = (threadIdx.x >= d) ? s[threadIdx.x - d] : 0;
        __syncthreads();
        s[threadIdx.x] += t;
        __syncthreads();
    }
    if (gid < N_NODES) g_rowptr[gid] = s[threadIdx.x] - v;
    if (threadIdx.x == SCAN_BLK - 1) g_bsum[blockIdx.x] = s[SCAN_BLK - 1];
}

__global__ void k_scanB() {
    if (threadIdx.x == 0) {
        int run = 0;
        for (int b = 0; b < N_SCAN_BLOCKS; b++) {
            g_bofs[b] = run;
            run += g_bsum[b];
        }
    }
}

__global__ void k_scanC() {
    int i = blockIdx.x * blockDim.x + threadIdx.x;
    if (i < N_NODES) {
        int r = g_rowptr[i] + g_bofs[i / SCAN_BLK];
        g_rowptr[i] = r;
        g_cur[i] = r;
    }
    if (i == 0) g_rowptr[N_NODES] = N_EDGES;
}

__global__ void k_scatter() {
    int e = blockIdx.x * blockDim.x + threadIdx.x;
    if (e < N_EDGES) {
        int src = g_src[e];
        int dst = g_dst[e];
        if ((unsigned)dst < N_NODES && (unsigned)src < N_NODES) {
            int pos = atomicAdd(&g_cur[dst], 1);
            g_col[pos] = src;
        }
    }
}

// ---------------- WMMA GEMM: C_half[M_PAD, BN] = A_f32[M,K] @ B_f32[K,BN] ----
// fp32 global operands converted to fp16 while staging to SMEM; fp32 accum;
// fp16 output (gather operand). BM=128, BK=32, 256 threads = 8 warps.
template <int BN, int WM, int WN>
__global__ __launch_bounds__(256) void gemm_wmma(
    const float* __restrict__ A, const float* __restrict__ B,
    __half* __restrict__ C, int M, int K)
{
    constexpr int BM = 128, BK = 32, PAD = 8;
    constexpr int WARPS_M = BM / WM;          // warp grid
    constexpr int MT = WM / 16, NT = WN / 16; // wmma tiles per warp
    static_assert((BM / WM) * (BN / WN) == 8, "8 warps");

    __shared__ __half As[BM][BK + PAD];
    __shared__ __half Bs[BK][BN + PAD];

    int tid = threadIdx.x;
    int warpId = tid >> 5;
    int wm = warpId % WARPS_M;
    int wn = warpId / WARPS_M;
    int row0 = blockIdx.x * BM;

    wmma::fragment<wmma::accumulator, 16, 16, 16, float> cf[MT][NT];
    #pragma unroll
    for (int i = 0; i < MT; i++)
        #pragma unroll
        for (int j = 0; j < NT; j++) wmma::fill_fragment(cf[i][j], 0.0f);

    for (int kt = 0; kt < K; kt += BK) {
        // stage A: 128 x 32 fp32 -> fp16 smem (8 float4 per row)
        #pragma unroll
        for (int i = tid; i < BM * BK / 4; i += 256) {
            int r  = i >> 3;           // /8
            int c4 = (i & 7) << 2;
            float4 v = make_float4(0.f, 0.f, 0.f, 0.f);
            if (row0 + r < M)
                v = *(const float4*)&A[(size_t)(row0 + r) * K + kt + c4];
            As[r][c4 + 0] = __float2half_rn(v.x);
            As[r][c4 + 1] = __float2half_rn(v.y);
            As[r][c4 + 2] = __float2half_rn(v.z);
            As[r][c4 + 3] = __float2half_rn(v.w);
        }
        // stage B: 32 x BN fp32 -> fp16 smem
        #pragma unroll
        for (int i = tid; i < BK * BN / 4; i += 256) {
            int r  = i / (BN / 4);
            int c4 = (i % (BN / 4)) << 2;
            float4 v = *(const float4*)&B[(size_t)(kt + r) * BN + c4];
            Bs[r][c4 + 0] = __float2half_rn(v.x);
            Bs[r][c4 + 1] = __float2half_rn(v.y);
            Bs[r][c4 + 2] = __float2half_rn(v.z);
            Bs[r][c4 + 3] = __float2half_rn(v.w);
        }
        __syncthreads();

        #pragma unroll
        for (int kk = 0; kk < BK; kk += 16) {
            wmma::fragment<wmma::matrix_a, 16, 16, 16, __half, wmma::row_major> af[MT];
            wmma::fragment<wmma::matrix_b, 16, 16, 16, __half, wmma::row_major> bf[NT];
            #pragma unroll
            for (int i = 0; i < MT; i++)
                wmma::load_matrix_sync(af[i], &As[wm * WM + i * 16][kk], BK + PAD);
            #pragma unroll
            for (int j = 0; j < NT; j++)
                wmma::load_matrix_sync(bf[j], &Bs[kk][wn * WN + j * 16], BN + PAD);
            #pragma unroll
            for (int i = 0; i < MT; i++)
                #pragma unroll
                for (int j = 0; j < NT; j++)
                    wmma::mma_sync(cf[i][j], af[i], bf[j], cf[i][j]);
        }
        __syncthreads();
    }

    // epilogue: fp32 accum fragment -> fp16 fragment -> global (rows padded; no guard)
    #pragma unroll
    for (int i = 0; i < MT; i++) {
        #pragma unroll
        for (int j = 0; j < NT; j++) {
            wmma::fragment<wmma::accumulator, 16, 16, 16, __half> hf;
            #pragma unroll
            for (int e = 0; e < cf[i][j].num_elements; e++)
                hf.x[e] = __float2half_rn(cf[i][j].x[e]);
            __half* dst = C + (size_t)(row0 + wm * WM + i * 16) * BN + wn * WN + j * 16;
            wmma::store_matrix_sync(dst, hf, BN, wmma::mem_row_major);
        }
    }
}

// ---------------- aggregation: out[i] = dis[i]*(dis[i]*h_i + sum dis[j]*h_j)+b
// one warp per dst node; lane owns 4 consecutive fp16 features (8B load/edge).
template <int F, bool RELU>
__global__ __launch_bounds__(256) void agg_kernel(
    const __half* __restrict__ h, float* __restrict__ out,
    const float* __restrict__ bias)
{
    int warp = (blockIdx.x * blockDim.x + threadIdx.x) >> 5;
    int lane = threadIdx.x & 31;
    if (warp >= N_NODES) return;

    constexpr int NCHUNK = F / 4;
    bool active = (NCHUNK == 32) || (lane < NCHUNK);

    float di = g_dis[warp];
    float4 acc = make_float4(0.f, 0.f, 0.f, 0.f);
    if (active) {
        const __half2* p = (const __half2*)(h + (size_t)warp * F + lane * 4);
        float2 u = __half22float2(p[0]);
        float2 v = __half22float2(p[1]);
        acc.x = di * u.x; acc.y = di * u.y; acc.z = di * v.x; acc.w = di * v.y;
    }

    int p   = g_rowptr[warp];
    int end = g_rowptr[warp + 1];

    for (; p + 4 <= end; p += 4) {
        int j0 = __ldg(&g_col[p + 0]);
        int j1 = __ldg(&g_col[p + 1]);
        int j2 = __ldg(&g_col[p + 2]);
        int j3 = __ldg(&g_col[p + 3]);
        float w0 = __ldg(&g_dis[j0]);
        float w1 = __ldg(&g_dis[j1]);
        float w2 = __ldg(&g_dis[j2]);
        float w3 = __ldg(&g_dis[j3]);
        if (active) {
            const __half2* q0 = (const __half2*)(h + (size_t)j0 * F + lane * 4);
            const __half2* q1 = (const __half2*)(h + (size_t)j1 * F + lane * 4);
            const __half2* q2 = (const __half2*)(h + (size_t)j2 * F + lane * 4);
            const __half2* q3 = (const __half2*)(h + (size_t)j3 * F + lane * 4);
            float2 a0 = __half22float2(q0[0]), b0 = __half22float2(q0[1]);
            float2 a1 = __half22float2(q1[0]), b1 = __half22float2(q1[1]);
            float2 a2 = __half22float2(q2[0]), b2 = __half22float2(q2[1]);
            float2 a3 = __half22float2(q3[0]), b3 = __half22float2(q3[1]);
            acc.x += w0 * a0.x + w1 * a1.x + w2 * a2.x + w3 * a3.x;
            acc.y += w0 * a0.y + w1 * a1.y + w2 * a2.y + w3 * a3.y;
            acc.z += w0 * b0.x + w1 * b1.x + w2 * b2.x + w3 * b3.x;
            acc.w += w0 * b0.y + w1 * b1.y + w2 * b2.y + w3 * b3.y;
        }
    }
    for (; p < end; p++) {
        int j = __ldg(&g_col[p]);
        float w = __ldg(&g_dis[j]);
        if (active) {
            const __half2* q = (const __half2*)(h + (size_t)j * F + lane * 4);
            float2 u = __half22float2(q[0]);
            float2 v = __half22float2(q[1]);
            acc.x += w * u.x; acc.y += w * u.y;
            acc.z += w * v.x; acc.w += w * v.y;
        }
    }

    if (active) {
        float4 b4 = *(const float4*)&bias[lane * 4];
        float4 o;
        o.x = di * acc.x + b4.x;
        o.y = di * acc.y + b4.y;
        o.z = di * acc.z + b4.z;
        o.w = di * acc.w + b4.w;
        if (RELU) {
            o.x = fmaxf(o.x, 0.f); o.y = fmaxf(o.y, 0.f);
            o.z = fmaxf(o.z, 0.f); o.w = fmaxf(o.w, 0.f);
        }
        *(float4*)&out[(size_t)warp * F + lane * 4] = o;
    }
}

// ---------------- launch ------------------------------------------------------
extern "C" void kernel_launch(void* const* d_in, const int* in_sizes, int n_in,
                              void* d_out, int out_size)
{
    const float* x  = (const float*)d_in[0];
    const void*  ei = d_in[1];
    const float* W1 = (const float*)d_in[2];
    const float* b1 = (const float*)d_in[3];
    const float* W2 = (const float*)d_in[4];
    const float* b2 = (const float*)d_in[5];
    const float* W3 = (const float*)d_in[6];
    const float* b3 = (const float*)d_in[7];
    float* out = (float*)d_out;

    __half* hbuf = nullptr;
    float*  abuf = nullptr;
    cudaGetSymbolAddress((void**)&hbuf, g_h);
    cudaGetSymbolAddress((void**)&abuf, g_a);

    const int TPB = 256;
    int nb_nodes = (N_NODES + TPB - 1) / TPB;
    int nb_edges = (N_EDGES + TPB - 1) / TPB;

    // --- CSR build ---
    k_detect<<<1, 64>>>((const int*)ei);
    k_zero_ecnt<<<nb_nodes, TPB>>>();
    k_prep<<<nb_edges, TPB>>>(ei);
    k_dis<<<nb_nodes, TPB>>>();
    k_scanA<<<N_SCAN_BLOCKS, SCAN_BLK>>>();
    k_scanB<<<1, 32>>>();
    k_scanC<<<nb_nodes, TPB>>>();
    k_scatter<<<nb_edges, TPB>>>();

    int gemm_blocks = (N_NODES + 127) / 128;   // 782
    int agg_blocks  = (N_NODES + 7) / 8;       // 8 warps per 256-thread block

    // --- layer 1: x[100000,256] @ W1[256,128] -> fp16 h -> agg+relu -> fp32 a
    gemm_wmma<128, 64, 32><<<gemm_blocks, 256>>>(x, W1, hbuf, N_NODES, IN_DIM);
    agg_kernel<128, true><<<agg_blocks, 256>>>(hbuf, abuf, b1);

    // --- layer 2: a @ W2[128,128] -> fp16 h -> agg+relu -> fp32 a
    gemm_wmma<128, 64, 32><<<gemm_blocks, 256>>>(abuf, W2, hbuf, N_NODES, HID_DIM);
    agg_kernel<128, true><<<agg_blocks, 256>>>(hbuf, abuf, b2);

    // --- layer 3: a @ W3[128,64] -> fp16 h -> agg (no relu) -> d_out fp32
    gemm_wmma<64, 32, 32><<<gemm_blocks, 256>>>(abuf, W3, hbuf, N_NODES, HID_DIM);
    agg_kernel<64, false><<<agg_blocks, 256>>>(hbuf, out, b3);
}

// round 7
// speedup vs baseline: 1.8169x; 1.3386x over previous
#include <cuda_runtime.h>
#include <cuda_fp16.h>
#include <mma.h>
#include <cstdint>

using namespace nvcuda;

#define N_NODES 100000
#define N_EDGES 3200000
#define IN_DIM  256
#define HID_DIM 128
#define OUT_DIM 64
#define M_PAD   100096          // 782 * 128, so WMMA stores need no tail guard

#define SCAN_BLK 1024
#define N_SCAN_BLOCKS ((N_NODES + SCAN_BLK - 1) / SCAN_BLK)   // 98

// ---------------- device scratch (static: no runtime allocation) -------------
__device__ int    g_is64;
__device__ int    g_src[N_EDGES];
__device__ int    g_dst[N_EDGES];
__device__ int    g_ecnt[N_NODES];
__device__ float  g_dis[N_NODES];
__device__ int    g_rowptr[N_NODES + 1];
__device__ int    g_cur[N_NODES];
__device__ int    g_col[N_EDGES];
__device__ int    g_bsum[N_SCAN_BLOCKS];
__device__ int    g_bofs[N_SCAN_BLOCKS];
__device__ __half g_h[(size_t)M_PAD * HID_DIM];   // dis-scaled transform output, fp16
__device__ float  g_a[(size_t)M_PAD * HID_DIM];   // aggregation output (GEMM input), fp32

// ---------------- init: zero histogram + edge dtype detect --------------------
// int64 values < 2^17 -> every odd 32-bit word is 0; int32 -> odd words random.
__global__ void k_init(const int* __restrict__ ei32) {
    int i = blockIdx.x * blockDim.x + threadIdx.x;
    if (i < N_NODES) g_ecnt[i] = 0;
    if (blockIdx.x == 0) {
        __shared__ int nz;
        if (threadIdx.x == 0) nz = 0;
        __syncthreads();
        int idx = 2 * threadIdx.x + 1;
        if (threadIdx.x < 64 && ei32[idx] != 0) atomicAdd(&nz, 1);
        __syncthreads();
        if (threadIdx.x == 0) g_is64 = (nz == 0) ? 1 : 0;
    }
}

// fused: normalize edge dtype + in-degree histogram (one pass over edge_index)
__global__ void k_prep(const void* __restrict__ ei) {
    int e = blockIdx.x * blockDim.x + threadIdx.x;
    if (e >= N_EDGES) return;
    int s, d;
    if (g_is64) {
        const long long* p = (const long long*)ei;
        s = (int)p[e];
        d = (int)p[N_EDGES + e];
    } else {
        const int* p = (const int*)ei;
        s = p[e];
        d = p[N_EDGES + e];
    }
    g_src[e] = s;
    g_dst[e] = d;
    if ((unsigned)d < N_NODES) atomicAdd(&g_ecnt[d], 1);
}

// block-level exclusive scan (also emits dis = rsqrt(deg+1))
__global__ void k_scanA() {
    __shared__ int s[SCAN_BLK];
    int gid = blockIdx.x * SCAN_BLK + threadIdx.x;
    int v = (gid < N_NODES) ? g_ecnt[gid] : 0;
    if (gid < N_NODES) g_dis[gid] = rsqrtf((float)(v + 1));
    s[threadIdx.x] = v;
    __syncthreads();
    #pragma unroll
    for (int d = 1; d < SCAN_BLK; d <<= 1) {
        int t = (threadIdx.x >= d) ? s[threadIdx.x - d] : 0;
        __syncthreads();
        s[threadIdx.x] += t;
        __syncthreads();
    }
    if (gid < N_NODES) g_rowptr[gid] = s[threadIdx.x] - v;
    if (threadIdx.x == SCAN_BLK - 1) g_bsum[blockIdx.x] = s[SCAN_BLK - 1];
}

__global__ void k_scanB() {
    if (threadIdx.x == 0) {
        int run = 0;
        for (int b = 0; b < N_SCAN_BLOCKS; b++) {
            g_bofs[b] = run;
            run += g_bsum[b];
        }
    }
}

__global__ void k_scanC() {
    int i = blockIdx.x * blockDim.x + threadIdx.x;
    if (i < N_NODES) {
        int r = g_rowptr[i] + g_bofs[i / SCAN_BLK];
        g_rowptr[i] = r;
        g_cur[i] = r;
    }
    if (i == 0) g_rowptr[N_NODES] = N_EDGES;
}

__global__ void k_scatter() {
    int e = blockIdx.x * blockDim.x + threadIdx.x;
    if (e < N_EDGES) {
        int src = g_src[e];
        int dst = g_dst[e];
        if ((unsigned)dst < N_NODES && (unsigned)src < N_NODES) {
            int pos = atomicAdd(&g_cur[dst], 1);
            g_col[pos] = src;
        }
    }
}

// ---------------- WMMA GEMM: C_half[r,:] = dis[r] * (A[r,:] @ B) --------------
// dis-scaling folded into the A staging (dis[r]*A_row). fp32->fp16 on stage,
// fp32 accum, fp16 output. BM=128, BK=32, 256 threads = 8 warps.
template <int BN, int WM, int WN>
__global__ __launch_bounds__(256) void gemm_wmma(
    const float* __restrict__ A, const float* __restrict__ B,
    __half* __restrict__ C, const float* __restrict__ dis, int M, int K)
{
    constexpr int BM = 128, BK = 32, PAD = 8;
    constexpr int WARPS_M = BM / WM;
    constexpr int MT = WM / 16, NT = WN / 16;
    static_assert((BM / WM) * (BN / WN) == 8, "8 warps");

    __shared__ __half As[BM][BK + PAD];
    __shared__ __half Bs[BK][BN + PAD];

    int tid = threadIdx.x;
    int warpId = tid >> 5;
    int wm = warpId % WARPS_M;
    int wn = warpId / WARPS_M;
    int row0 = blockIdx.x * BM;

    wmma::fragment<wmma::accumulator, 16, 16, 16, float> cf[MT][NT];
    #pragma unroll
    for (int i = 0; i < MT; i++)
        #pragma unroll
        for (int j = 0; j < NT; j++) wmma::fill_fragment(cf[i][j], 0.0f);

    for (int kt = 0; kt < K; kt += BK) {
        // stage A: 128 x 32 fp32 -> dis-scaled fp16 smem (8 float4 per row)
        #pragma unroll
        for (int i = tid; i < BM * BK / 4; i += 256) {
            int r  = i >> 3;
            int c4 = (i & 7) << 2;
            float4 v = make_float4(0.f, 0.f, 0.f, 0.f);
            int grow = row0 + r;
            if (grow < M) {
                v = *(const float4*)&A[(size_t)grow * K + kt + c4];
                float w = __ldg(&dis[grow]);
                v.x *= w; v.y *= w; v.z *= w; v.w *= w;
            }
            As[r][c4 + 0] = __float2half_rn(v.x);
            As[r][c4 + 1] = __float2half_rn(v.y);
            As[r][c4 + 2] = __float2half_rn(v.z);
            As[r][c4 + 3] = __float2half_rn(v.w);
        }
        // stage B: 32 x BN fp32 -> fp16 smem
        #pragma unroll
        for (int i = tid; i < BK * BN / 4; i += 256) {
            int r  = i / (BN / 4);
            int c4 = (i % (BN / 4)) << 2;
            float4 v = *(const float4*)&B[(size_t)(kt + r) * BN + c4];
            Bs[r][c4 + 0] = __float2half_rn(v.x);
            Bs[r][c4 + 1] = __float2half_rn(v.y);
            Bs[r][c4 + 2] = __float2half_rn(v.z);
            Bs[r][c4 + 3] = __float2half_rn(v.w);
        }
        __syncthreads();

        #pragma unroll
        for (int kk = 0; kk < BK; kk += 16) {
            wmma::fragment<wmma::matrix_a, 16, 16, 16, __half, wmma::row_major> af[MT];
            wmma::fragment<wmma::matrix_b, 16, 16, 16, __half, wmma::row_major> bf[NT];
            #pragma unroll
            for (int i = 0; i < MT; i++)
                wmma::load_matrix_sync(af[i], &As[wm * WM + i * 16][kk], BK + PAD);
            #pragma unroll
            for (int j = 0; j < NT; j++)
                wmma::load_matrix_sync(bf[j], &Bs[kk][wn * WN + j * 16], BN + PAD);
            #pragma unroll
            for (int i = 0; i < MT; i++)
                #pragma unroll
                for (int j = 0; j < NT; j++)
                    wmma::mma_sync(cf[i][j], af[i], bf[j], cf[i][j]);
        }
        __syncthreads();
    }

    #pragma unroll
    for (int i = 0; i < MT; i++) {
        #pragma unroll
        for (int j = 0; j < NT; j++) {
            wmma::fragment<wmma::accumulator, 16, 16, 16, __half> hf;
            #pragma unroll
            for (int e = 0; e < cf[i][j].num_elements; e++)
                hf.x[e] = __float2half_rn(cf[i][j].x[e]);
            __half* dst = C + (size_t)(row0 + wm * WM + i * 16) * BN + wn * WN + j * 16;
            wmma::store_matrix_sync(dst, hf, BN, wmma::mem_row_major);
        }
    }
}

// ---------------- aggregation --------------------------------------------------
// h' rows are pre-scaled by dis[src]. out[i] = dis[i]*(h'_i + sum_j h'_j) + b.
// GROUP lanes cooperate on one dst node; each lane owns 4 fp16 features (8B).
// GROUP=32 for F=128, GROUP=16 for F=64 (2 nodes per warp).
template <int F, int GROUP, bool RELU>
__global__ __launch_bounds__(256) void agg_kernel(
    const __half* __restrict__ h, float* __restrict__ out,
    const float* __restrict__ bias)
{
    static_assert(F == GROUP * 4, "lane owns 4 features");
    int gtid = blockIdx.x * blockDim.x + threadIdx.x;
    int node = gtid / GROUP;
    int lane = gtid % GROUP;
    if (node >= N_NODES) return;

    // self term (h' already dis-scaled)
    const __half2* ps = (const __half2*)(h + (size_t)node * F + lane * 4);
    float2 su = __half22float2(ps[0]);
    float2 sv = __half22float2(ps[1]);
    float4 acc = make_float4(su.x, su.y, sv.x, sv.y);

    int p   = g_rowptr[node];
    int end = g_rowptr[node + 1];

    for (; p + 4 <= end; p += 4) {
        int j0 = __ldg(&g_col[p + 0]);
        int j1 = __ldg(&g_col[p + 1]);
        int j2 = __ldg(&g_col[p + 2]);
        int j3 = __ldg(&g_col[p + 3]);
        const __half2* q0 = (const __half2*)(h + (size_t)j0 * F + lane * 4);
        const __half2* q1 = (const __half2*)(h + (size_t)j1 * F + lane * 4);
        const __half2* q2 = (const __half2*)(h + (size_t)j2 * F + lane * 4);
        const __half2* q3 = (const __half2*)(h + (size_t)j3 * F + lane * 4);
        float2 a0 = __half22float2(q0[0]), b0 = __half22float2(q0[1]);
        float2 a1 = __half22float2(q1[0]), b1 = __half22float2(q1[1]);
        float2 a2 = __half22float2(q2[0]), b2 = __half22float2(q2[1]);
        float2 a3 = __half22float2(q3[0]), b3 = __half22float2(q3[1]);
        acc.x += (a0.x + a1.x) + (a2.x + a3.x);
        acc.y += (a0.y + a1.y) + (a2.y + a3.y);
        acc.z += (b0.x + b1.x) + (b2.x + b3.x);
        acc.w += (b0.y + b1.y) + (b2.y + b3.y);
    }
    for (; p < end; p++) {
        int j = __ldg(&g_col[p]);
        const __half2* q = (const __half2*)(h + (size_t)j * F + lane * 4);
        float2 u = __half22float2(q[0]);
        float2 v = __half22float2(q[1]);
        acc.x += u.x; acc.y += u.y; acc.z += v.x; acc.w += v.y;
    }

    float di = __ldg(&g_dis[node]);
    float4 b4 = *(const float4*)&bias[lane * 4];
    float4 o;
    o.x = di * acc.x + b4.x;
    o.y = di * acc.y + b4.y;
    o.z = di * acc.z + b4.z;
    o.w = di * acc.w + b4.w;
    if (RELU) {
        o.x = fmaxf(o.x, 0.f); o.y = fmaxf(o.y, 0.f);
        o.z = fmaxf(o.z, 0.f); o.w = fmaxf(o.w, 0.f);
    }
    *(float4*)&out[(size_t)node * F + lane * 4] = o;
}

// ---------------- launch ------------------------------------------------------
extern "C" void kernel_launch(void* const* d_in, const int* in_sizes, int n_in,
                              void* d_out, int out_size)
{
    const float* x  = (const float*)d_in[0];
    const void*  ei = d_in[1];
    const float* W1 = (const float*)d_in[2];
    const float* b1 = (const float*)d_in[3];
    const float* W2 = (const float*)d_in[4];
    const float* b2 = (const float*)d_in[5];
    const float* W3 = (const float*)d_in[6];
    const float* b3 = (const float*)d_in[7];
    float* out = (float*)d_out;

    __half* hbuf = nullptr;
    float*  abuf = nullptr;
    float*  disb = nullptr;
    cudaGetSymbolAddress((void**)&hbuf, g_h);
    cudaGetSymbolAddress((void**)&abuf, g_a);
    cudaGetSymbolAddress((void**)&disb, g_dis);

    const int TPB = 256;
    int nb_nodes = (N_NODES + TPB - 1) / TPB;
    int nb_edges = (N_EDGES + TPB - 1) / TPB;

    // --- CSR build (6 launches) ---
    k_init<<<nb_nodes, TPB>>>((const int*)ei);
    k_prep<<<nb_edges, TPB>>>(ei);
    k_scanA<<<N_SCAN_BLOCKS, SCAN_BLK>>>();
    k_scanB<<<1, 32>>>();
    k_scanC<<<nb_nodes, TPB>>>();
    k_scatter<<<nb_edges, TPB>>>();

    int gemm_blocks = (N_NODES + 127) / 128;                 // 782
    int agg_blocks_128 = (N_NODES * 32 + TPB - 1) / TPB;     // GROUP=32
    int agg_blocks_64  = (N_NODES * 16 + TPB - 1) / TPB;     // GROUP=16

    // --- layer 1: h' = dis*(x @ W1) -> agg+relu -> a
    gemm_wmma<128, 64, 32><<<gemm_blocks, 256>>>(x, W1, hbuf, disb, N_NODES, IN_DIM);
    agg_kernel<128, 32, true><<<agg_blocks_128, 256>>>(hbuf, abuf, b1);

    // --- layer 2: h' = dis*(a @ W2) -> agg+relu -> a
    gemm_wmma<128, 64, 32><<<gemm_blocks, 256>>>(abuf, W2, hbuf, disb, N_NODES, HID_DIM);
    agg_kernel<128, 32, true><<<agg_blocks_128, 256>>>(hbuf, abuf, b2);

    // --- layer 3: h' = dis*(a @ W3) -> agg (no relu) -> d_out
    gemm_wmma<64, 32, 32><<<gemm_blocks, 256>>>(abuf, W3, hbuf, disb, N_NODES, HID_DIM);
    agg_kernel<64, 16, false><<<agg_blocks_64, 256>>>(hbuf, out, b3);
}